// round 4
// baseline (speedup 1.0000x reference)
#include <cuda_runtime.h>

#define VOCABSZ 50000
#define EMSIZE  300
#define NBINS   5
#define BB      32
#define QQ      16
#define DD      10
#define LL      1000
#define CHUNKS  38      // 37 chunks of 8 e-cols + 1 chunk of 4 (300 = 37*8 + 4)

typedef unsigned long long ull;

// ---------------- device scratch (no allocations allowed) ----------------
__device__ float g_invnorm[VOCABSZ];
__device__ float g_qn[BB * EMSIZE * QQ];   // [b][e][q], pre-normalized query embeddings
__device__ float g_tbl[BB * QQ * NBINS];   // tw[b,q] * w1[n]
__device__ float g_logits[BB * QQ];
__device__ float g_c0[BB];
__device__ float g_c1;

// ---------------- helpers ----------------
__device__ __forceinline__ ull fma2(ull a, ull b, ull c) {
    ull d;
    asm("fma.rn.f32x2 %0, %1, %2, %3;" : "=l"(d) : "l"(a), "l"(b), "l"(c));
    return d;
}
__device__ __forceinline__ ull dup2(float x) {
    ull d;
    asm("mov.b64 %0, {%1, %1};" : "=l"(d) : "r"(__float_as_uint(x)));
    return d;
}
__device__ __forceinline__ void unpack2(ull p, float& lo, float& hi) {
    unsigned a, b;
    asm("mov.b64 {%0, %1}, %2;" : "=r"(a), "=r"(b) : "l"(p));
    lo = __uint_as_float(a);
    hi = __uint_as_float(b);
}
__device__ __forceinline__ float warp_sum(float v) {
#pragma unroll
    for (int o = 16; o > 0; o >>= 1) v += __shfl_xor_sync(0xffffffffu, v, o);
    return v;
}
__device__ __forceinline__ void cp16(unsigned dst, const void* src) {
    asm volatile("cp.async.ca.shared.global [%0], [%1], 16;\n" :: "r"(dst), "l"(src));
}
__device__ __forceinline__ void cp_commit() {
    asm volatile("cp.async.commit_group;\n" ::: "memory");
}
__device__ __forceinline__ void cp_wait1() {
    asm volatile("cp.async.wait_group 1;\n" ::: "memory");
}
__device__ __forceinline__ void cp_wait0() {
    asm volatile("cp.async.wait_group 0;\n" ::: "memory");
}

// bin semantics from reference: [-1,-.5) [-0.5,0) [0,.5) [.5,1) and {==1.0};
// out-of-range values fall into no bin (contribute 0).
__device__ __forceinline__ float contrib(float v, const float* t5) {
    if (v < -1.0f) return 0.0f;
    if (v < -0.5f) return t5[0];
    if (v <  0.0f) return t5[1];
    if (v <  0.5f) return t5[2];
    if (v <  1.0f) return t5[3];
    return (v == 1.0f) ? t5[4] : 0.0f;
}

// ---------------- K0: per-vocab inverse norms ----------------
__global__ void k_vocab_norms(const float* __restrict__ emb) {
    int w = (blockIdx.x * blockDim.x + threadIdx.x) >> 5;
    int lane = threadIdx.x & 31;
    if (w >= VOCABSZ) return;
    const float* row = emb + (size_t)w * EMSIZE;
    float s = 0.0f;
    for (int e = lane; e < EMSIZE; e += 32) {
        float v = row[e];
        s += v * v;
    }
    s = warp_sum(s);
    if (lane == 0) g_invnorm[w] = 1.0f / sqrtf(s);
}

// ---------------- K1: gather + normalize query embeddings, gate logits ----------------
__global__ void k_query_prep(const int* __restrict__ queries, const float* __restrict__ emb,
                             const float* __restrict__ gate_w, const float* __restrict__ gate_b) {
    int w = (blockIdx.x * blockDim.x + threadIdx.x) >> 5;  // (b,q) index 0..511
    int lane = threadIdx.x & 31;
    if (w >= BB * QQ) return;
    int b = w >> 4, q = w & 15;
    int tok = queries[w];
    const float* row = emb + (size_t)tok * EMSIZE;
    float vv[10];
    float s = 0.0f, g = 0.0f;
    int n = 0;
    for (int e = lane; e < EMSIZE; e += 32) {
        float v = row[e];
        vv[n++] = v;
        s += v * v;
        g += v * gate_w[e];
    }
    s = warp_sum(s);
    g = warp_sum(g);
    float invn = 1.0f / sqrtf(s);
    if (lane == 0) g_logits[w] = g + gate_b[0];
    n = 0;
    for (int e = lane; e < EMSIZE; e += 32) {
        g_qn[b * (EMSIZE * QQ) + e * QQ + q] = vv[n++] * invn;  // transposed [e][q]
    }
}

// ---------------- K2: softmax over query terms + fused scalar constants ----------------
__global__ void k_softmax(const float* __restrict__ w1, const float* __restrict__ b1,
                          const float* __restrict__ w2, const float* __restrict__ b2,
                          const float* __restrict__ ow, const float* __restrict__ ob) {
    int t = threadIdx.x;  // 512 threads: b = t/16, q = t%16
    int b = t >> 4, q = t & 15;
    float logit = g_logits[t];
    float m = logit;
#pragma unroll
    for (int o = 8; o > 0; o >>= 1) m = fmaxf(m, __shfl_xor_sync(0xffffffffu, m, o, 16));
    float e = expf(logit - m);
    float sum = e;
#pragma unroll
    for (int o = 8; o > 0; o >>= 1) sum += __shfl_xor_sync(0xffffffffu, sum, o, 16);
    float tw = e / sum;
    float tws = tw;
#pragma unroll
    for (int o = 8; o > 0; o >>= 1) tws += __shfl_xor_sync(0xffffffffu, tws, o, 16);
#pragma unroll
    for (int n = 0; n < NBINS; n++) g_tbl[(b * QQ + q) * NBINS + n] = tw * w1[n];
    if (q == 0) g_c0[b] = ob[0] + ow[0] * (w2[0] * b1[0] + b2[0]) * tws;
    if (t == 0) g_c1 = ow[0] * w2[0];
}

// ---------------- K3: main — one CTA per (b,d); per-warp-private doc pipeline, no mainloop barriers
// smem layout (floats):
//   qs  [300][16]                              4800
//   ds  [8 warps][2 buf][2 half][128 rows][4] 16384
//   tbl [16*5]                                   80
//   red [8]                                       8
// total 21272 floats = 85088 B -> 2 CTAs/SM = 170176 B (fits 228KB)
#define SMEM_FLOATS 21272

__global__ __launch_bounds__(256, 2) void k_main(const int* __restrict__ docs,
                                                 const float* __restrict__ emb,
                                                 float* __restrict__ out) {
    extern __shared__ float sm[];
    float* qs  = sm;              // 4800
    float* ds  = sm + 4800;       // 16384
    float* tbl = sm + 21184;      // 80
    float* red = sm + 21264;      // 8

    const int t = threadIdx.x;
    const int w = t >> 5, lane = t & 31;
    const int bb = blockIdx.x / DD, dd = blockIdx.x % DD;

    // --- prologue: shared q-tile + table (one barrier) ---
    {
        const float4* src = (const float4*)(g_qn + bb * (EMSIZE * QQ));
        float4* dst = (float4*)qs;
        for (int i = t; i < (EMSIZE * QQ) / 4; i += 256) dst[i] = src[i];
    }
    if (t < QQ * NBINS) tbl[t] = g_tbl[bb * QQ * NBINS + t];

    // --- per-thread doc rows: l = 128*w + lane + 32*j, j=0..3 (l>=1000 masked) ---
    const int* dix = docs + (bb * DD + dd) * LL;
    int   idx[4];
    float invn[4];
#pragma unroll
    for (int j = 0; j < 4; j++) {
        int l = 128 * w + lane + 32 * j;
        idx[j]  = (l < LL) ? dix[l] : 0;
        invn[j] = g_invnorm[idx[j]];
    }
    __syncthreads();   // qs/tbl visible

    // per-warp private double buffer: 2 bufs x (2 halves x 128 rows x 4 floats)
    float* myds = ds + w * 2048;

    // issue chunk c into buf: 32B contiguous per row (2 x cp16), split halves
    auto issue = [&](int c, int buf) {
        const int e0 = c * 8;
        const bool full = (c < 37);
        float* db = myds + buf * 1024;
        unsigned dst0 = (unsigned)__cvta_generic_to_shared(db + lane * 4);
#pragma unroll
        for (int j = 0; j < 4; j++) {
            const float* s = emb + (size_t)idx[j] * EMSIZE + e0;
            cp16(dst0 + j * 512, s);                    // half 0: e0..e0+3
            if (full) cp16(dst0 + 2048 + j * 512, s + 4);  // half 1: e0+4..e0+7
        }
        cp_commit();
    };

    // --- accumulators: 16 queries (8 f32x2 pairs) x 4 doc rows per thread ---
    ull acc[8][4];
#pragma unroll
    for (int i = 0; i < 8; i++)
#pragma unroll
        for (int m = 0; m < 4; m++) acc[i][m] = 0ull;

    issue(0, 0);

    int buf = 0;
    for (int c = 0; c < CHUNKS; c++) {
        if (c + 1 < CHUNKS) {
            issue(c + 1, buf ^ 1);
            cp_wait1();     // chunk c landed; c+1 still in flight
        } else {
            cp_wait0();
        }
        const float* db = myds + buf * 1024;
        const int nh = (c < 37) ? 2 : 1;   // last chunk: 4 cols only
#pragma unroll
        for (int h = 0; h < 2; h++) {
            if (h >= nh) break;
            // this thread's 4 doc rows, 4 e-cols each (LDS.128, conflict-free)
            float4 d0 = *(const float4*)(db + h * 512 + lane * 4);
            float4 d1 = *(const float4*)(db + h * 512 + lane * 4 + 512 * 1 - 512 * 0 + 0);  // placeholder
            // (explicit per-j loads below)
            (void)d1;
            float4 dr[4];
#pragma unroll
            for (int j = 0; j < 4; j++)
                dr[j] = *(const float4*)(db + h * 512 + (lane + 32 * j) * 4);
            (void)d0;
#pragma unroll
            for (int e = 0; e < 4; e++) {
                const int ecol = c * 8 + h * 4 + e;
                const ull* qr = (const ull*)(qs + ecol * QQ);
                ull q[8];
#pragma unroll
                for (int qp = 0; qp < 8; qp++) q[qp] = qr[qp];
                ull b0 = dup2(((const float*)&dr[0])[e]);
                ull b1 = dup2(((const float*)&dr[1])[e]);
                ull b2 = dup2(((const float*)&dr[2])[e]);
                ull b3 = dup2(((const float*)&dr[3])[e]);
#pragma unroll
                for (int qp = 0; qp < 8; qp++) {
                    acc[qp][0] = fma2(q[qp], b0, acc[qp][0]);
                    acc[qp][1] = fma2(q[qp], b1, acc[qp][1]);
                    acc[qp][2] = fma2(q[qp], b2, acc[qp][2]);
                    acc[qp][3] = fma2(q[qp], b3, acc[qp][3]);
                }
            }
        }
        buf ^= 1;
    }

    // --- epilogue: bin each cosine, accumulate tw*w1[bin] ---
    float s = 0.0f;
#pragma unroll
    for (int j = 0; j < 4; j++) {
        int l = 128 * w + lane + 32 * j;
        if (l < LL) {
            float inl = invn[j];
#pragma unroll
            for (int qp = 0; qp < 8; qp++) {
                float lo, hi;
                unpack2(acc[qp][j], lo, hi);
                s += contrib(lo * inl, tbl + (2 * qp) * NBINS);
                s += contrib(hi * inl, tbl + (2 * qp + 1) * NBINS);
            }
        }
    }
    s = warp_sum(s);
    if (lane == 0) red[w] = s;
    __syncthreads();
    if (t == 0) {
        float tot = 0.0f;
#pragma unroll
        for (int i = 0; i < 8; i++) tot += red[i];
        out[bb * DD + dd] = g_c0[bb] + g_c1 * tot;
    }
}

// ---------------- launch ----------------
extern "C" void kernel_launch(void* const* d_in, const int* in_sizes, int n_in,
                              void* d_out, int out_size) {
    const int*   queries = (const int*)d_in[0];
    const int*   docs    = (const int*)d_in[1];
    const float* emb     = (const float*)d_in[2];
    const float* gate_w  = (const float*)d_in[3];
    const float* gate_b  = (const float*)d_in[4];
    const float* w1      = (const float*)d_in[5];
    const float* b1      = (const float*)d_in[6];
    const float* w2      = (const float*)d_in[7];
    const float* b2      = (const float*)d_in[8];
    const float* ow      = (const float*)d_in[9];
    const float* ob      = (const float*)d_in[10];
    float* out = (float*)d_out;

    cudaFuncSetAttribute(k_main, cudaFuncAttributeMaxDynamicSharedMemorySize,
                         SMEM_FLOATS * (int)sizeof(float));

    // K0: vocab inverse norms (warp per row)
    k_vocab_norms<<<(VOCABSZ * 32 + 255) / 256, 256>>>(emb);
    // K1: query prep (warp per (b,q))
    k_query_prep<<<(BB * QQ * 32 + 255) / 256, 256>>>(queries, emb, gate_w, gate_b);
    // K2: softmax + constant folding
    k_softmax<<<1, BB * QQ>>>(w1, b1, w2, b2, ow, ob);
    // K3: main scoring kernel, one CTA per (b,d)
    k_main<<<BB * DD, 256, SMEM_FLOATS * (int)sizeof(float)>>>(docs, emb, out);
}

// round 5
// speedup vs baseline: 1.2234x; 1.2234x over previous
#include <cuda_runtime.h>

#define VOCABSZ 50000
#define EMSIZE  300
#define NBINS   5
#define BB      32
#define QQ      16
#define DD      10
#define LL      1000
#define NCHUNK  19        // 18 chunks of 16 e-cols + 1 of 12 (300 = 18*16+12)
#define PITCH   20        // floats per row slot (16 data + 4 pad)

typedef unsigned long long ull;

// ---------------- device scratch ----------------
__device__ float g_invnorm[VOCABSZ];
__device__ float g_qn[BB * EMSIZE * QQ];   // [b][e][q] normalized query embeddings
__device__ float g_tbl[BB * QQ * NBINS];   // tw[b,q] * w1[n]
__device__ float g_logits[BB * QQ];
__device__ float g_c0[BB];
__device__ float g_c1;
__device__ float g_part[BB * DD * 2];      // per-half-CTA partial sums

// ---------------- helpers ----------------
__device__ __forceinline__ ull fma2(ull a, ull b, ull c) {
    ull d;
    asm("fma.rn.f32x2 %0, %1, %2, %3;" : "=l"(d) : "l"(a), "l"(b), "l"(c));
    return d;
}
__device__ __forceinline__ ull dup2(float x) {
    ull d;
    asm("mov.b64 %0, {%1, %1};" : "=l"(d) : "r"(__float_as_uint(x)));
    return d;
}
__device__ __forceinline__ void unpack2(ull p, float& lo, float& hi) {
    unsigned a, b;
    asm("mov.b64 {%0, %1}, %2;" : "=r"(a), "=r"(b) : "l"(p));
    lo = __uint_as_float(a);
    hi = __uint_as_float(b);
}
__device__ __forceinline__ float warp_sum(float v) {
#pragma unroll
    for (int o = 16; o > 0; o >>= 1) v += __shfl_xor_sync(0xffffffffu, v, o);
    return v;
}
__device__ __forceinline__ void cp16(unsigned dst, const void* src) {
    asm volatile("cp.async.ca.shared.global [%0], [%1], 16;\n" :: "r"(dst), "l"(src));
}
__device__ __forceinline__ void cp_commit() {
    asm volatile("cp.async.commit_group;\n" ::: "memory");
}
__device__ __forceinline__ void cp_wait1() {
    asm volatile("cp.async.wait_group 1;\n" ::: "memory");
}
__device__ __forceinline__ void cp_wait0() {
    asm volatile("cp.async.wait_group 0;\n" ::: "memory");
}

// bins: [-1,-.5) [-0.5,0) [0,.5) [.5,1) and {==1.0}; out-of-range -> 0
__device__ __forceinline__ float contrib(float v, const float* t5) {
    if (v < -1.0f) return 0.0f;
    if (v < -0.5f) return t5[0];
    if (v <  0.0f) return t5[1];
    if (v <  0.5f) return t5[2];
    if (v <  1.0f) return t5[3];
    return (v == 1.0f) ? t5[4] : 0.0f;
}

// ---------------- K0: per-vocab inverse norms (also warms L2 with the table) ----
__global__ void k_vocab_norms(const float* __restrict__ emb) {
    int w = (blockIdx.x * blockDim.x + threadIdx.x) >> 5;
    int lane = threadIdx.x & 31;
    if (w >= VOCABSZ) return;
    const float* row = emb + (size_t)w * EMSIZE;
    float s = 0.0f;
    for (int e = lane; e < EMSIZE; e += 32) {
        float v = row[e];
        s += v * v;
    }
    s = warp_sum(s);
    if (lane == 0) g_invnorm[w] = 1.0f / sqrtf(s);
}

// ---------------- K1: query gather+normalize, gate logits ----------------
__global__ void k_query_prep(const int* __restrict__ queries, const float* __restrict__ emb,
                             const float* __restrict__ gate_w, const float* __restrict__ gate_b) {
    int w = (blockIdx.x * blockDim.x + threadIdx.x) >> 5;
    int lane = threadIdx.x & 31;
    if (w >= BB * QQ) return;
    int b = w >> 4, q = w & 15;
    int tok = queries[w];
    const float* row = emb + (size_t)tok * EMSIZE;
    float vv[10];
    float s = 0.0f, g = 0.0f;
    int n = 0;
    for (int e = lane; e < EMSIZE; e += 32) {
        float v = row[e];
        vv[n++] = v;
        s += v * v;
        g += v * gate_w[e];
    }
    s = warp_sum(s);
    g = warp_sum(g);
    float invn = 1.0f / sqrtf(s);
    if (lane == 0) g_logits[w] = g + gate_b[0];
    n = 0;
    for (int e = lane; e < EMSIZE; e += 32)
        g_qn[b * (EMSIZE * QQ) + e * QQ + q] = vv[n++] * invn;
}

// ---------------- K2: softmax + constant folding ----------------
__global__ void k_softmax(const float* __restrict__ w1, const float* __restrict__ b1,
                          const float* __restrict__ w2, const float* __restrict__ b2,
                          const float* __restrict__ ow, const float* __restrict__ ob) {
    int t = threadIdx.x;  // 512
    int b = t >> 4, q = t & 15;
    float logit = g_logits[t];
    float m = logit;
#pragma unroll
    for (int o = 8; o > 0; o >>= 1) m = fmaxf(m, __shfl_xor_sync(0xffffffffu, m, o, 16));
    float e = expf(logit - m);
    float sum = e;
#pragma unroll
    for (int o = 8; o > 0; o >>= 1) sum += __shfl_xor_sync(0xffffffffu, sum, o, 16);
    float tw = e / sum;
    float tws = tw;
#pragma unroll
    for (int o = 8; o > 0; o >>= 1) tws += __shfl_xor_sync(0xffffffffu, tws, o, 16);
#pragma unroll
    for (int n = 0; n < NBINS; n++) g_tbl[(b * QQ + q) * NBINS + n] = tw * w1[n];
    if (q == 0) g_c0[b] = ob[0] + ow[0] * (w2[0] * b1[0] + b2[0]) * tws;
    if (t == 0) g_c1 = ow[0] * w2[0];
}

// ---------------- K3: main — 2 CTAs per (b,d), 512 doc rows each, 256 threads
// Warp w owns local rows [64w, 64w+64): thread lane owns rows 64w+lane, 64w+lane+32.
// Per-warp-private double-buffered doc tile, e-chunks of 16, 64B-coalesced cp.async.
// smem floats: qs 4800 | ds 8*2*64*PITCH=20480 | tbl 80 | red 8  -> 25368 fl = 101472 B
#define SMEM_FLOATS 25368

__global__ __launch_bounds__(256, 2) void k_main(const int* __restrict__ docs,
                                                 const float* __restrict__ emb) {
    extern __shared__ float sm[];
    float* qs  = sm;               // 4800
    float* ds  = sm + 4800;        // 20480
    float* tbl = sm + 25280;       // 80
    float* red = sm + 25360;       // 8

    const int t = threadIdx.x;
    const int w = t >> 5, lane = t & 31;
    const int bd = blockIdx.x >> 1;            // (b,d) index
    const int half = blockIdx.x & 1;           // which 512-row half
    const int bb = bd / DD;

    // --- prologue: q tile + table ---
    {
        const float4* src = (const float4*)(g_qn + bb * (EMSIZE * QQ));
        float4* dst = (float4*)qs;
        for (int i = t; i < (EMSIZE * QQ) / 4; i += 256) dst[i] = src[i];
    }
    if (t < QQ * NBINS) tbl[t] = g_tbl[bb * QQ * NBINS + t];

    const int* dix = docs + bd * LL;
    const int rbase = half * 512 + w * 64;     // global l of this warp's row 0

    // gather-role indices: this thread fetches seg (lane>>3) of rows j*8+(lane&7)
    const int r8 = lane & 7, sg = lane >> 3;
    int gidx[8];
#pragma unroll
    for (int j = 0; j < 8; j++) {
        int l = rbase + j * 8 + r8;
        gidx[j] = (l < LL) ? dix[l] : 0;
    }
    // owner-role: rows lane, lane+32
    const int l0 = rbase + lane, l1 = rbase + lane + 32;
    const float invn0 = (l0 < LL) ? g_invnorm[dix[l0]] : 0.0f;
    const float invn1 = (l1 < LL) ? g_invnorm[dix[l1]] : 0.0f;
    __syncthreads();   // qs/tbl visible

    float* myds = ds + w * (2 * 64 * PITCH);   // per-warp private, 2 buffers

    auto issue = [&](int c, int buf) {
        const int e0 = c * 16;
        const int nseg = (c < 18) ? 4 : 3;     // last chunk: 12 cols
        if (sg < nseg) {
            float* db = myds + buf * (64 * PITCH);
            unsigned d0 = (unsigned)__cvta_generic_to_shared(db + r8 * PITCH + sg * 4);
#pragma unroll
            for (int j = 0; j < 8; j++)
                cp16(d0 + j * (8 * PITCH * 4), emb + (size_t)gidx[j] * EMSIZE + e0 + sg * 4);
        }
        cp_commit();
    };

    // accumulators: 16 q (8 f32x2) x 2 rows
    ull acc[8][2];
#pragma unroll
    for (int i = 0; i < 8; i++) { acc[i][0] = 0ull; acc[i][1] = 0ull; }

    issue(0, 0);

    int buf = 0;
    for (int c = 0; c < NCHUNK; c++) {
        if (c + 1 < NCHUNK) {
            issue(c + 1, buf ^ 1);
            cp_wait1();
        } else {
            cp_wait0();
        }
        const float* db = myds + buf * (64 * PITCH);
        const int nq = (c < 18) ? 4 : 3;
#pragma unroll
        for (int k = 0; k < 4; k++) {
            if (k >= nq) break;
            float4 dA = *(const float4*)(db + lane * PITCH + k * 4);
            float4 dB = *(const float4*)(db + (lane + 32) * PITCH + k * 4);
#pragma unroll
            for (int e = 0; e < 4; e++) {
                const float* qb = qs + (c * 16 + k * 4 + e) * QQ;
                float4 qv[4];
#pragma unroll
                for (int i = 0; i < 4; i++) qv[i] = ((const float4*)qb)[i];
                const ull* qq = (const ull*)qv;
                ull bA = dup2(((const float*)&dA)[e]);
                ull bB = dup2(((const float*)&dB)[e]);
#pragma unroll
                for (int qp = 0; qp < 8; qp++) {
                    acc[qp][0] = fma2(qq[qp], bA, acc[qp][0]);
                    acc[qp][1] = fma2(qq[qp], bB, acc[qp][1]);
                }
            }
        }
        buf ^= 1;
    }

    // --- epilogue: bin cosines, accumulate tw*w1[bin] ---
    float s = 0.0f;
    if (l0 < LL) {
#pragma unroll
        for (int qp = 0; qp < 8; qp++) {
            float lo, hi;
            unpack2(acc[qp][0], lo, hi);
            s += contrib(lo * invn0, tbl + (2 * qp) * NBINS);
            s += contrib(hi * invn0, tbl + (2 * qp + 1) * NBINS);
        }
    }
    if (l1 < LL) {
#pragma unroll
        for (int qp = 0; qp < 8; qp++) {
            float lo, hi;
            unpack2(acc[qp][1], lo, hi);
            s += contrib(lo * invn1, tbl + (2 * qp) * NBINS);
            s += contrib(hi * invn1, tbl + (2 * qp + 1) * NBINS);
        }
    }
    s = warp_sum(s);
    if (lane == 0) red[w] = s;
    __syncthreads();
    if (t == 0) {
        float tot = 0.0f;
#pragma unroll
        for (int i = 0; i < 8; i++) tot += red[i];
        g_part[blockIdx.x] = tot;
    }
}

// ---------------- K4: deterministic combine ----------------
__global__ void k_final(float* __restrict__ out) {
    int i = threadIdx.x;   // 320
    out[i] = g_c0[i / DD] + g_c1 * (g_part[2 * i] + g_part[2 * i + 1]);
}

// ---------------- launch ----------------
extern "C" void kernel_launch(void* const* d_in, const int* in_sizes, int n_in,
                              void* d_out, int out_size) {
    const int*   queries = (const int*)d_in[0];
    const int*   docs    = (const int*)d_in[1];
    const float* emb     = (const float*)d_in[2];
    const float* gate_w  = (const float*)d_in[3];
    const float* gate_b  = (const float*)d_in[4];
    const float* w1      = (const float*)d_in[5];
    const float* b1      = (const float*)d_in[6];
    const float* w2      = (const float*)d_in[7];
    const float* b2      = (const float*)d_in[8];
    const float* ow      = (const float*)d_in[9];
    const float* ob      = (const float*)d_in[10];
    float* out = (float*)d_out;

    cudaFuncSetAttribute(k_main, cudaFuncAttributeMaxDynamicSharedMemorySize,
                         SMEM_FLOATS * (int)sizeof(float));

    k_vocab_norms<<<(VOCABSZ * 32 + 255) / 256, 256>>>(emb);
    k_query_prep<<<(BB * QQ * 32 + 255) / 256, 256>>>(queries, emb, gate_w, gate_b);
    k_softmax<<<1, BB * QQ>>>(w1, b1, w2, b2, ow, ob);
    k_main<<<BB * DD * 2, 256, SMEM_FLOATS * (int)sizeof(float)>>>(docs, emb);
    k_final<<<1, BB * DD>>>(out);
}